// round 2
// baseline (speedup 1.0000x reference)
#include <cuda_runtime.h>
#include <cuda_bf16.h>
#include <cstddef>

// Problem constants
#define B_  4
#define C_  256
#define H_  64
#define W_  64
#define P_  (H_*W_)       // 4096
#define COMP_ 64
#define SCALE_ 2
#define S2_ 4
#define KUP_ 5
#define K2_ 25
#define KENC_ 3
#define EPS_ 1e-5f

// Scratch (device globals; no allocation)
__device__ float g_act[B_ * COMP_ * P_];            // (4,64,64,64)   4.19 MB
__device__ float g_mask[B_ * K2_ * S2_ * P_];       // (4,25,4,64,64) 16.8 MB

// ---------------------------------------------------------------------------
// Kernel 1: 1x1 compression conv + BatchNorm(eval) + SiLU
// grid (B*32, 2), block 128. Each block: 128 pixels, 32 of the 64 outputs.
// ---------------------------------------------------------------------------
__global__ __launch_bounds__(128) void k_compress(
    const float* __restrict__ x, const float* __restrict__ w_comp,
    const float* __restrict__ gamma, const float* __restrict__ beta,
    const float* __restrict__ mean, const float* __restrict__ var)
{
    __shared__ float ws[256][32];   // [c][o_local], broadcast-friendly
    const int ohalf = blockIdx.y;
    const int b = blockIdx.x >> 5;
    const int p = ((blockIdx.x & 31) << 7) + threadIdx.x;

    // Load w slice: ws[c][o] = w_comp[(ohalf*32+o)*256 + c]
    for (int i = threadIdx.x; i < 32 * 256; i += 128) {
        int o = i & 31, c = i >> 5;
        ws[c][o] = w_comp[(ohalf * 32 + o) * 256 + c];
    }
    __syncthreads();

    float acc[32];
#pragma unroll
    for (int o = 0; o < 32; o++) acc[o] = 0.f;

    const float* xb = x + ((size_t)b * C_) * P_ + p;
#pragma unroll 4
    for (int c = 0; c < 256; c++) {
        float xv = xb[(size_t)c * P_];
        const float4* w4 = (const float4*)ws[c];
#pragma unroll
        for (int j = 0; j < 8; j++) {
            float4 w = w4[j];
            acc[4 * j + 0] += w.x * xv;
            acc[4 * j + 1] += w.y * xv;
            acc[4 * j + 2] += w.z * xv;
            acc[4 * j + 3] += w.w * xv;
        }
    }

#pragma unroll
    for (int o = 0; o < 32; o++) {
        int oc = ohalf * 32 + o;
        float sc = gamma[oc] * rsqrtf(var[oc] + EPS_);
        float v = (acc[o] - mean[oc]) * sc + beta[oc];
        float a = v / (1.f + __expf(-v));          // SiLU
        g_act[((size_t)b * COMP_ + oc) * P_ + p] = a;
    }
}

// ---------------------------------------------------------------------------
// Kernel 2: 3x3 encoder conv (64 -> 25 per s-slice) + softmax over k (25)
// grid (16 tiles, 4 s, 4 b), block 256 (16x16 pixels).
// Dynamic smem: act tile 64*18*18 + w slice 25*64*12 (padded rows).
// ---------------------------------------------------------------------------
#define K2_ACT_FLOATS (64 * 18 * 18)        // 20736
#define K2_W_FLOATS   (25 * 64 * 12)        // 19200 (9 used, 3 pad)
#define K2_SMEM_BYTES ((K2_ACT_FLOATS + K2_W_FLOATS) * 4)

__global__ __launch_bounds__(256) void k_encoder(const float* __restrict__ w_enc)
{
    extern __shared__ float sm[];
    float* act_s = sm;                     // [ci][yy][xx] pitch 18
    float* w_s   = sm + K2_ACT_FLOATS;     // [k][ci][12]

    const int s = blockIdx.y;
    const int b = blockIdx.z;
    const int tile = blockIdx.x;
    const int ty0 = (tile >> 2) * 16, tx0 = (tile & 3) * 16;
    const int tid = threadIdx.x;

    // Load w slice for this s: w_enc[(k*4+s)*576 + ci*9 + q] -> w_s[k*768 + ci*12 + q]
    for (int i = tid; i < 25 * 576; i += 256) {
        int k = i / 576, rem = i % 576;
        int ci = rem / 9, q = rem % 9;
        w_s[k * 768 + ci * 12 + q] = w_enc[(k * 4 + s) * 576 + rem];
    }
    // Load act tile with pad=1 (zero-fill OOB)
    for (int i = tid; i < K2_ACT_FLOATS; i += 256) {
        int ci = i / 324, r = i % 324;
        int yy = r / 18, xx = r % 18;
        int gy = ty0 + yy - 1, gx = tx0 + xx - 1;
        float v = 0.f;
        if ((unsigned)gy < 64u && (unsigned)gx < 64u)
            v = g_act[((size_t)b * COMP_ + ci) * P_ + gy * 64 + gx];
        act_s[i] = v;
    }
    __syncthreads();

    const int py = tid >> 4, px = tid & 15;
    float acc[25];
#pragma unroll
    for (int k = 0; k < 25; k++) acc[k] = 0.f;

    for (int ci = 0; ci < 64; ci++) {
        float a[9];
        const float* ap = act_s + ci * 324 + py * 18 + px;
#pragma unroll
        for (int dy = 0; dy < 3; dy++)
#pragma unroll
            for (int dx = 0; dx < 3; dx++)
                a[dy * 3 + dx] = ap[dy * 18 + dx];

        const float4* wbase = (const float4*)(w_s + ci * 12);
#pragma unroll
        for (int k = 0; k < 25; k++) {
            const float4* wk = wbase + k * 192;   // k*768 floats / 4
            float4 w0 = wk[0], w1 = wk[1], w2 = wk[2];
            float t = w0.x * a[0] + w0.y * a[1] + w0.z * a[2] +
                      w0.w * a[3] + w1.x * a[4] + w1.y * a[5] +
                      w1.z * a[6] + w1.w * a[7] + w2.x * a[8];
            acc[k] += t;
        }
    }

    // softmax over the 25 k values
    float m = acc[0];
#pragma unroll
    for (int k = 1; k < 25; k++) m = fmaxf(m, acc[k]);
    float sum = 0.f;
#pragma unroll
    for (int k = 0; k < 25; k++) { acc[k] = __expf(acc[k] - m); sum += acc[k]; }
    float inv = 1.f / sum;

    const int gy = ty0 + py, gx = tx0 + px;
#pragma unroll
    for (int k = 0; k < 25; k++)
        g_mask[(((size_t)b * K2_ + k) * S2_ + s) * P_ + gy * 64 + gx] = acc[k] * inv;
}

// ---------------------------------------------------------------------------
// Kernel 3: content-aware reassembly + pixel shuffle
// grid (64 tiles of 8x8, 8 cgroups of 32, 4 b), block 256 = 64 px * 4 csub.
// ---------------------------------------------------------------------------
__global__ __launch_bounds__(256, 1) void k_reassemble(
    const float* __restrict__ x, float* __restrict__ out)
{
    __shared__ float xs[32][144];       // [c_local][12x12]
    __shared__ float ms[25][4][64];     // [k][s][px]

    const int b = blockIdx.z;
    const int cg = blockIdx.y;
    const int tile = blockIdx.x;
    const int ty0 = (tile >> 3) * 8, tx0 = (tile & 7) * 8;
    const int tid = threadIdx.x;

    // Load x tile (halo 2, zero pad)
    for (int i = tid; i < 32 * 144; i += 256) {
        int cl = i / 144, r = i % 144;
        int yy = r / 12, xx = r % 12;
        int gy = ty0 + yy - 2, gx = tx0 + xx - 2;
        float v = 0.f;
        if ((unsigned)gy < 64u && (unsigned)gx < 64u)
            v = x[(((size_t)b * C_ + cg * 32 + cl) * 64 + gy) * 64 + gx];
        xs[cl][r] = v;
    }
    // Load mask tile
    for (int i = tid; i < 25 * 4 * 64; i += 256) {
        int k = i >> 8, rem = i & 255;
        int s = rem >> 6, px = rem & 63;
        int gy = ty0 + (px >> 3), gx = tx0 + (px & 7);
        ms[k][s][px] = g_mask[(((size_t)b * K2_ + k) * S2_ + s) * P_ + gy * 64 + gx];
    }
    __syncthreads();

    const int csub = tid >> 6, px = tid & 63;
    const int py = px >> 3, pxl = px & 7;

    // Cache the 100 mask values for this pixel in registers
    float mk[100];
#pragma unroll
    for (int k = 0; k < 25; k++)
#pragma unroll
        for (int s = 0; s < 4; s++)
            mk[s * 25 + k] = ms[k][s][px];

    const int gy = ty0 + py, gx = tx0 + pxl;

#pragma unroll
    for (int cc = 0; cc < 8; cc++) {
        int cl = csub * 8 + cc;
        float xr[25];
#pragma unroll
        for (int dy = 0; dy < 5; dy++)
#pragma unroll
            for (int dx = 0; dx < 5; dx++)
                xr[dy * 5 + dx] = xs[cl][(py + dy) * 12 + pxl + dx];

        float a0 = 0.f, a1 = 0.f, a2 = 0.f, a3 = 0.f;
#pragma unroll
        for (int k = 0; k < 25; k++) {
            a0 += mk[0 * 25 + k] * xr[k];
            a1 += mk[1 * 25 + k] * xr[k];
            a2 += mk[2 * 25 + k] * xr[k];
            a3 += mk[3 * 25 + k] * xr[k];
        }

        int c = cg * 32 + cl;
        size_t base = (((size_t)b * C_ + c) * 128 + 2 * gy) * 128 + 2 * gx;
        *(float2*)(out + base)       = make_float2(a0, a1);   // s=(0,0),(0,1)
        *(float2*)(out + base + 128) = make_float2(a2, a3);   // s=(1,0),(1,1)
    }
}

// ---------------------------------------------------------------------------
extern "C" void kernel_launch(void* const* d_in, const int* in_sizes, int n_in,
                              void* d_out, int out_size)
{
    const float* x       = (const float*)d_in[0];
    const float* w_comp  = (const float*)d_in[1];
    const float* bn_g    = (const float*)d_in[2];
    const float* bn_b    = (const float*)d_in[3];
    const float* bn_m    = (const float*)d_in[4];
    const float* bn_v    = (const float*)d_in[5];
    const float* w_enc   = (const float*)d_in[6];
    float* out = (float*)d_out;

    cudaFuncSetAttribute(k_encoder, cudaFuncAttributeMaxDynamicSharedMemorySize,
                         K2_SMEM_BYTES);

    dim3 g1(B_ * 32, 2);
    k_compress<<<g1, 128>>>(x, w_comp, bn_g, bn_b, bn_m, bn_v);

    dim3 g2(16, 4, B_);
    k_encoder<<<g2, 256, K2_SMEM_BYTES>>>(w_enc);

    dim3 g3(64, 8, B_);
    k_reassemble<<<g3, 256>>>(x, out);
}

// round 3
// speedup vs baseline: 2.0439x; 2.0439x over previous
#include <cuda_runtime.h>
#include <cuda_bf16.h>
#include <cstddef>

// Problem constants
#define B_  4
#define C_  256
#define H_  64
#define W_  64
#define P_  (H_*W_)       // 4096
#define COMP_ 64
#define S2_ 4
#define K2_ 25
#define EPS_ 1e-5f
#define MPAD_ 28          // mask row padded to 28 floats (16B-aligned rows)

// Scratch (device globals; no allocation)
__device__ float g_act[B_ * COMP_ * P_];                 // (4,64,64,64)   4.19 MB
__device__ float g_mask2[B_ * S2_ * P_ * MPAD_];         // [b][s][p][28]  7.34 MB

// ---------------------------------------------------------------------------
// Kernel 1: 1x1 compression conv + BatchNorm(eval) + SiLU
// grid (16 pxblocks, 8 outgroups, 4 b), block 256. Thread: 1 pixel x 8 outputs.
// 131K threads (43% occ).
// ---------------------------------------------------------------------------
__global__ __launch_bounds__(256) void k_compress(
    const float* __restrict__ x, const float* __restrict__ w_comp,
    const float* __restrict__ gamma, const float* __restrict__ beta,
    const float* __restrict__ mean, const float* __restrict__ var)
{
    __shared__ float ws[256][8];    // [c][o_local]
    const int og = blockIdx.y;      // 8 groups of 8 outputs
    const int b  = blockIdx.z;
    const int p  = (blockIdx.x << 8) + threadIdx.x;

    for (int i = threadIdx.x; i < 256 * 8; i += 256) {
        int o = i & 7, c = i >> 3;
        ws[c][o] = w_comp[(og * 8 + o) * 256 + c];
    }
    __syncthreads();

    float acc[8];
#pragma unroll
    for (int o = 0; o < 8; o++) acc[o] = 0.f;

    const float* xb = x + ((size_t)b * C_) * P_ + p;
#pragma unroll 8
    for (int c = 0; c < 256; c++) {
        float xv = xb[(size_t)c * P_];
        float4 w0 = *(const float4*)&ws[c][0];
        float4 w1 = *(const float4*)&ws[c][4];
        acc[0] += w0.x * xv; acc[1] += w0.y * xv;
        acc[2] += w0.z * xv; acc[3] += w0.w * xv;
        acc[4] += w1.x * xv; acc[5] += w1.y * xv;
        acc[6] += w1.z * xv; acc[7] += w1.w * xv;
    }

#pragma unroll
    for (int o = 0; o < 8; o++) {
        int oc = og * 8 + o;
        float sc = gamma[oc] * rsqrtf(var[oc] + EPS_);
        float v = (acc[o] - mean[oc]) * sc + beta[oc];
        float a = v / (1.f + __expf(-v));          // SiLU
        g_act[((size_t)b * COMP_ + oc) * P_ + p] = a;
    }
}

// ---------------------------------------------------------------------------
// Kernel 2: 3x3 encoder conv (64->25 per s-slice) + softmax over k (25)
// grid (16 tiles, 4 s, 4 b), block 256 (16x16 px). Two passes over ci (32+32)
// keep smem at ~80KB -> 2 blocks/SM (16 warps/SM).
// Writes mask in [b][s][p][28] layout via float4 stores.
// ---------------------------------------------------------------------------
#define ENC_ACT_FLOATS (32 * 18 * 18)        // 10368
#define ENC_W_FLOATS   (25 * 32 * 12)        // 9600 (rows padded 9->12)
#define ENC_SMEM_BYTES ((ENC_ACT_FLOATS + ENC_W_FLOATS) * 4)   // 79872

__global__ __launch_bounds__(256) void k_encoder(const float* __restrict__ w_enc)
{
    extern __shared__ float sm[];
    float* act_s = sm;                      // [cl][yy][xx] pitch 18 (32 ch)
    float* w_s   = sm + ENC_ACT_FLOATS;     // [k][cl][12]

    const int s = blockIdx.y;
    const int b = blockIdx.z;
    const int tile = blockIdx.x;
    const int ty0 = (tile >> 2) * 16, tx0 = (tile & 3) * 16;
    const int tid = threadIdx.x;
    const int py = tid >> 4, px = tid & 15;

    float acc[25];
#pragma unroll
    for (int k = 0; k < 25; k++) acc[k] = 0.f;

    for (int pass = 0; pass < 2; pass++) {
        if (pass) __syncthreads();          // previous compute done before overwrite
        const int ci0 = pass * 32;

        // load w slice: w_s[k*384 + cl*12 + q] = w_enc[(k*4+s)*576 + (ci0+cl)*9 + q]
        for (int i = tid; i < 25 * 288; i += 256) {
            int k = i / 288, rem = i % 288;
            int cl = rem / 9, q = rem % 9;
            w_s[k * 384 + cl * 12 + q] = w_enc[(k * 4 + s) * 576 + (ci0 + cl) * 9 + q];
        }
        // load act tile (pad=1, zero-fill)
        for (int i = tid; i < ENC_ACT_FLOATS; i += 256) {
            int cl = i / 324, r = i % 324;
            int yy = r / 18, xx = r % 18;
            int gy = ty0 + yy - 1, gx = tx0 + xx - 1;
            float v = 0.f;
            if ((unsigned)gy < 64u && (unsigned)gx < 64u)
                v = g_act[((size_t)b * COMP_ + ci0 + cl) * P_ + gy * 64 + gx];
            act_s[i] = v;
        }
        __syncthreads();

        for (int cl = 0; cl < 32; cl++) {
            float a[9];
            const float* ap = act_s + cl * 324 + py * 18 + px;
#pragma unroll
            for (int dy = 0; dy < 3; dy++)
#pragma unroll
                for (int dx = 0; dx < 3; dx++)
                    a[dy * 3 + dx] = ap[dy * 18 + dx];

            const float4* wbase = (const float4*)(w_s + cl * 12);
#pragma unroll
            for (int k = 0; k < 25; k++) {
                const float4* wk = wbase + k * 96;   // k*384 floats / 4
                float4 w0 = wk[0], w1 = wk[1], w2 = wk[2];
                acc[k] += w0.x * a[0] + w0.y * a[1] + w0.z * a[2] +
                          w0.w * a[3] + w1.x * a[4] + w1.y * a[5] +
                          w1.z * a[6] + w1.w * a[7] + w2.x * a[8];
            }
        }
    }

    // softmax over 25 k values
    float m = acc[0];
#pragma unroll
    for (int k = 1; k < 25; k++) m = fmaxf(m, acc[k]);
    float sum = 0.f;
#pragma unroll
    for (int k = 0; k < 25; k++) { acc[k] = __expf(acc[k] - m); sum += acc[k]; }
    float inv = 1.f / sum;
#pragma unroll
    for (int k = 0; k < 25; k++) acc[k] *= inv;

    // store [b][s][p][28], 7x STG.128
    const int gp = (ty0 + py) * 64 + tx0 + px;
    float4* mp = (float4*)(g_mask2 + (((size_t)b * S2_ + s) * P_ + gp) * MPAD_);
    mp[0] = make_float4(acc[0],  acc[1],  acc[2],  acc[3]);
    mp[1] = make_float4(acc[4],  acc[5],  acc[6],  acc[7]);
    mp[2] = make_float4(acc[8],  acc[9],  acc[10], acc[11]);
    mp[3] = make_float4(acc[12], acc[13], acc[14], acc[15]);
    mp[4] = make_float4(acc[16], acc[17], acc[18], acc[19]);
    mp[5] = make_float4(acc[20], acc[21], acc[22], acc[23]);
    mp[6] = make_float4(acc[24], 0.f, 0.f, 0.f);
}

// ---------------------------------------------------------------------------
// Kernel 3: content-aware reassembly + pixel shuffle
// grid (64 tiles of 8x8, 8 cgroups of 32, 4 b), block 256 = 64 px * 4 csub.
// Mask read from [b][s][p][28] layout via float4 gmem->smem.
// ---------------------------------------------------------------------------
__global__ __launch_bounds__(256, 2) void k_reassemble(
    const float* __restrict__ x, float* __restrict__ out)
{
    __shared__ float xs[32][144];        // [c_local][12x12]   18.4KB
    __shared__ float ms[256][MPAD_];     // [(s*64+px)][k]     28.7KB

    const int b = blockIdx.z;
    const int cg = blockIdx.y;
    const int tile = blockIdx.x;
    const int ty0 = (tile >> 3) * 8, tx0 = (tile & 7) * 8;
    const int tid = threadIdx.x;

    // x tile (halo 2, zero pad)
    for (int i = tid; i < 32 * 144; i += 256) {
        int cl = i / 144, r = i % 144;
        int yy = r / 12, xx = r % 12;
        int gy = ty0 + yy - 2, gx = tx0 + xx - 2;
        float v = 0.f;
        if ((unsigned)gy < 64u && (unsigned)gx < 64u)
            v = x[(((size_t)b * C_ + cg * 32 + cl) * 64 + gy) * 64 + gx];
        xs[cl][r] = v;
    }
    // mask tile: 256 rows x 7 float4 (L2-resident)
    for (int i = tid; i < 256 * 7; i += 256) {
        int row = i / 7, j = i % 7;
        int s = row >> 6, px = row & 63;
        int gp = (ty0 + (px >> 3)) * 64 + tx0 + (px & 7);
        const float4* src = (const float4*)(g_mask2 + (((size_t)b * S2_ + s) * P_ + gp) * MPAD_);
        *((float4*)ms[row] + j) = src[j];
    }
    __syncthreads();

    const int csub = tid >> 6, px = tid & 63;
    const int py = px >> 3, pxl = px & 7;

    // cache 100 mask values for this pixel in registers
    float mk[4][25];
#pragma unroll
    for (int s = 0; s < 4; s++)
#pragma unroll
        for (int k = 0; k < 25; k++)
            mk[s][k] = ms[s * 64 + px][k];

    const int gy = ty0 + py, gx = tx0 + pxl;

#pragma unroll
    for (int cc = 0; cc < 8; cc++) {
        int cl = csub * 8 + cc;
        float xr[25];
#pragma unroll
        for (int dy = 0; dy < 5; dy++)
#pragma unroll
            for (int dx = 0; dx < 5; dx++)
                xr[dy * 5 + dx] = xs[cl][(py + dy) * 12 + pxl + dx];

        float a0 = 0.f, a1 = 0.f, a2 = 0.f, a3 = 0.f;
#pragma unroll
        for (int k = 0; k < 25; k++) {
            a0 += mk[0][k] * xr[k];
            a1 += mk[1][k] * xr[k];
            a2 += mk[2][k] * xr[k];
            a3 += mk[3][k] * xr[k];
        }

        int c = cg * 32 + cl;
        size_t base = (((size_t)b * C_ + c) * 128 + 2 * gy) * 128 + 2 * gx;
        *(float2*)(out + base)       = make_float2(a0, a1);   // s=(0,0),(0,1)
        *(float2*)(out + base + 128) = make_float2(a2, a3);   // s=(1,0),(1,1)
    }
}

// ---------------------------------------------------------------------------
extern "C" void kernel_launch(void* const* d_in, const int* in_sizes, int n_in,
                              void* d_out, int out_size)
{
    const float* x       = (const float*)d_in[0];
    const float* w_comp  = (const float*)d_in[1];
    const float* bn_g    = (const float*)d_in[2];
    const float* bn_b    = (const float*)d_in[3];
    const float* bn_m    = (const float*)d_in[4];
    const float* bn_v    = (const float*)d_in[5];
    const float* w_enc   = (const float*)d_in[6];
    float* out = (float*)d_out;

    cudaFuncSetAttribute(k_encoder, cudaFuncAttributeMaxDynamicSharedMemorySize,
                         ENC_SMEM_BYTES);

    dim3 g1(16, 8, B_);
    k_compress<<<g1, 256>>>(x, w_comp, bn_g, bn_b, bn_m, bn_v);

    dim3 g2(16, 4, B_);
    k_encoder<<<g2, 256, ENC_SMEM_BYTES>>>(w_enc);

    dim3 g3(64, 8, B_);
    k_reassemble<<<g3, 256>>>(x, out);
}